// round 16
// baseline (speedup 1.0000x reference)
#include <cuda_runtime.h>
#include <cuda_fp16.h>
#include <cstdint>

// Problem constants
#define Cdim 1024
#define Hn   16
#define En   64
#define Mtok 25088          // B*N
#define Lseq 3136           // f*N
#define NBGRP 8
#define SCALE_Q 0.125f
#define EPS_V   1e-6f
#define KVP  7              // kv sequence partitions

#define N4X  (Mtok * (Cdim / 4))
#define N4WQ (3072 * Cdim / 4)
#define N4WP (Cdim * Cdim / 4)
#define N4ALL (N4X + N4WQ + N4WP)

// Scratch (static device memory)
__device__ float g_kv  [NBGRP * Hn * En * En];
__device__ float g_ksum[NBGRP * Hn * En];
__device__ float g_kvp [KVP][NBGRP * Hn * En * En];
__device__ float g_ksp [KVP][NBGRP * Hn * En];
// fp16 tensors
__device__ __half g_xh[(size_t)Mtok * Cdim];
__device__ __half g_qh[(size_t)Mtok * Cdim];
__device__ __half g_kh[(size_t)Mtok * Cdim];
__device__ __half g_vh[(size_t)Mtok * Cdim];
__device__ __half g_ah[(size_t)Mtok * Cdim];
__device__ __half g_wqh[3072 * Cdim];
__device__ __half g_wph[Cdim * Cdim];

// ---------------------------------------------------------------------------
// Helpers
// ---------------------------------------------------------------------------
__device__ __forceinline__ uint32_t smem_u32(const void* p) {
    uint32_t a;
    asm("{ .reg .u64 t; cvta.to.shared.u64 t, %1; cvt.u32.u64 %0, t; }" : "=r"(a) : "l"(p));
    return a;
}

__device__ __forceinline__ void mma16816(float* d, const uint32_t* a,
                                         uint32_t b0, uint32_t b1) {
    asm volatile(
        "mma.sync.aligned.m16n8k16.row.col.f32.f16.f16.f32 "
        "{%0,%1,%2,%3}, {%4,%5,%6,%7}, {%8,%9}, {%0,%1,%2,%3};"
        : "+f"(d[0]), "+f"(d[1]), "+f"(d[2]), "+f"(d[3])
        : "r"(a[0]), "r"(a[1]), "r"(a[2]), "r"(a[3]), "r"(b0), "r"(b1));
}

__device__ __forceinline__ void ldsm4(uint32_t addr, uint32_t* r) {
    asm volatile("ldmatrix.sync.aligned.m8n8.x4.shared.b16 {%0,%1,%2,%3}, [%4];"
                 : "=r"(r[0]), "=r"(r[1]), "=r"(r[2]), "=r"(r[3]) : "r"(addr));
}

#define CP16(dst, src) \
    asm volatile("cp.async.cg.shared.global [%0], [%1], 16;" :: "r"(dst), "l"(src))
#define CP_COMMIT() asm volatile("cp.async.commit_group;" ::: "memory")
#define CP_WAIT1()  asm volatile("cp.async.wait_group 1;" ::: "memory")

// Swizzled byte offset for 128-byte rows: quad (16B) XOR row&7
__device__ __forceinline__ uint32_t swz(uint32_t row, uint32_t quad) {
    return (row << 7) + ((quad ^ (row & 7)) << 4);
}

// ---------------------------------------------------------------------------
// Fused fp32 -> fp16 conversion (x, w_qkv, w_proj), 8 floats per thread
// ---------------------------------------------------------------------------
__global__ __launch_bounds__(256)
void conv_all(const float4* __restrict__ x, const float4* __restrict__ wq,
              const float4* __restrict__ wp)
{
    #pragma unroll
    for (int r = 0; r < 2; r++) {
        int i = (blockIdx.x * 2 + r) * 256 + threadIdx.x;
        const float4* src; __half* dst; int j;
        if (i < N4X)             { src = x;  dst = g_xh;  j = i; }
        else if (i < N4X + N4WQ) { src = wq; dst = g_wqh; j = i - N4X; }
        else if (i < N4ALL)      { src = wp; dst = g_wph; j = i - N4X - N4WQ; }
        else continue;
        float4 v = src[j];
        __half2 h01 = __floats2half2_rn(v.x, v.y);
        __half2 h23 = __floats2half2_rn(v.z, v.w);
        *(uint2*)&dst[(size_t)j * 4] = make_uint2(*(uint32_t*)&h01, *(uint32_t*)&h23);
    }
}

// ---------------------------------------------------------------------------
// FP16 tensor-core NT GEMM. Block 128x128, K-chunk 64, 4 warps (2m x 2n),
// warp tile 64x64. cp.async for chunk c+2 spread ONE PAIR PER MMA ITERATION
// (fully even LSU issue); A frags double-buffered per k-step, B per
// iteration. NSTG=3, wait_group 1, 2 CTAs/SM.
// ---------------------------------------------------------------------------
#define ARR_SZ 16384
#define STG_B (2 * ARR_SZ)
#define NSTG 3
#define GEMM_SMEM (NSTG * STG_B)

template<int MODE>
__global__ __launch_bounds__(128, 2)
void gemm_tc(const __half* __restrict__ A_g,
             const __half* __restrict__ W_g,
             const float* __restrict__ bias, float* __restrict__ out)
{
    extern __shared__ __align__(128) char smem[];
    const uint32_t sbase = smem_u32(smem);
    const int tid  = threadIdx.x;
    const int lane = tid & 31;
    const int w    = tid >> 5;
    const int wm   = w & 1;
    const int wn   = w >> 1;
    const int m0 = blockIdx.y * 128;
    const int n0 = blockIdx.x * 128;

    const int a_row = (lane & 7) + ((lane >> 3) & 1) * 8;
    const int a_kq  = (lane >> 4) & 1;
    const int b_row = (lane & 7) + (lane >> 4) * 8;
    const int b_kq  = (lane >> 3) & 1;

    auto issue = [&](int c) {
        const uint32_t st = sbase + (c % NSTG) * STG_B;
        const int k0 = c * 64;
        #pragma unroll
        for (int p = 0; p < 8; p++) {
            int id = tid + p * 128;
            int row = id >> 3, quad = id & 7;
            uint32_t so = swz(row, quad);
            CP16(st + so, A_g + (size_t)(m0 + row) * Cdim + k0 + quad * 8);
            CP16(st + ARR_SZ + so, W_g + (size_t)(n0 + row) * Cdim + k0 + quad * 8);
        }
    };

    float acc[4][8][4];
    #pragma unroll
    for (int mt = 0; mt < 4; mt++)
        #pragma unroll
        for (int nt = 0; nt < 8; nt++)
            #pragma unroll
            for (int r = 0; r < 4; r++) acc[mt][nt][r] = 0.0f;

    issue(0); CP_COMMIT();
    issue(1); CP_COMMIT();

    for (int c = 0; c < 16; c++) {
        CP_WAIT1();
        __syncthreads();

        const bool pf = (c + 2 < 16);
        const uint32_t st2 = sbase + ((c + 2) % NSTG) * STG_B;
        const int k02 = (c + 2) * 64;

        const uint32_t st = sbase + (c % NSTG) * STG_B;
        const uint32_t sA = st, sB = st + ARR_SZ;

        // A double-buffer at ks granularity; B double-buffer per iteration
        uint32_t ah[2][4][4];
        #pragma unroll
        for (int mt = 0; mt < 4; mt++) {
            uint32_t row = wm * 64 + mt * 16 + a_row;
            ldsm4(sA + swz(row, 0 * 2 + a_kq), ah[0][mt]);
        }
        uint32_t bf[2][4];
        {
            uint32_t row = wn * 64 + 0 * 16 + b_row;
            ldsm4(sB + swz(row, 0 * 2 + b_kq), bf[0]);
        }
        #pragma unroll
        for (int it = 0; it < 16; it++) {
            const int ks = it >> 2, bt = it & 3;
            // spread next-chunk cp.async: one A OR B quad per iteration
            if (pf) {
                int half16 = it >> 3;            // 0: A rows, 1: B rows
                int p = it & 7;
                int id = tid + p * 128;
                int row = id >> 3, quad = id & 7;
                uint32_t so = swz(row, quad);
                if (half16 == 0)
                    CP16(st2 + so, A_g + (size_t)(m0 + row) * Cdim + k02 + quad * 8);
                else
                    CP16(st2 + ARR_SZ + so, W_g + (size_t)(n0 + row) * Cdim + k02 + quad * 8);
            }
            // prefetch next B fragment
            if (it + 1 < 16) {
                const int ks2 = (it + 1) >> 2, bt2 = (it + 1) & 3;
                uint32_t row = wn * 64 + bt2 * 16 + b_row;
                ldsm4(sB + swz(row, ks2 * 2 + b_kq), bf[(it + 1) & 1]);
            }
            // prefetch one A fragment of ks+1 per iteration
            if (ks < 3) {
                const int mt = bt;
                uint32_t row = wm * 64 + mt * 16 + a_row;
                ldsm4(sA + swz(row, (ks + 1) * 2 + a_kq), ah[(ks + 1) & 1][mt]);
            }
            const uint32_t* bh = bf[it & 1];
            #pragma unroll
            for (int half = 0; half < 2; half++) {
                const int nt = bt * 2 + half;
                #pragma unroll
                for (int mt = 0; mt < 4; mt++)
                    mma16816(acc[mt][nt], ah[ks & 1][mt], bh[half * 2], bh[half * 2 + 1]);
            }
        }
        CP_COMMIT();
    }

    const int r4 = lane >> 2, c4 = lane & 3;
    if (MODE == 0) {
        const int sN = n0 >> 10;                 // 0:q 1:k 2:v
        __half* dst = (sN == 0) ? g_qh : (sN == 1) ? g_kh : g_vh;
        const int colb = (n0 & 1023) + wn * 64;
        #pragma unroll
        for (int mt = 0; mt < 4; mt++) {
            #pragma unroll
            for (int nt = 0; nt < 8; nt++) {
                float v0 = acc[mt][nt][0], v1 = acc[mt][nt][1];
                float v2 = acc[mt][nt][2], v3 = acc[mt][nt][3];
                if (sN < 2) {
                    v0 = fmaxf(v0, 0.0f) + SCALE_Q;
                    v1 = fmaxf(v1, 0.0f) + SCALE_Q;
                    v2 = fmaxf(v2, 0.0f) + SCALE_Q;
                    v3 = fmaxf(v3, 0.0f) + SCALE_Q;
                }
                int m = m0 + wm * 64 + mt * 16 + r4;
                int col = colb + nt * 8 + c4 * 2;
                __half2 h01 = __floats2half2_rn(v0, v1);
                __half2 h23 = __floats2half2_rn(v2, v3);
                *(uint32_t*)(dst + (size_t)m * Cdim + col)       = *(uint32_t*)&h01;
                *(uint32_t*)(dst + (size_t)(m + 8) * Cdim + col) = *(uint32_t*)&h23;
            }
        }
    } else {
        #pragma unroll
        for (int mt = 0; mt < 4; mt++) {
            #pragma unroll
            for (int nt = 0; nt < 8; nt++) {
                int m = m0 + wm * 64 + mt * 16 + r4;
                int col = n0 + wn * 64 + nt * 8 + c4 * 2;
                float b0 = __ldg(bias + col), b1 = __ldg(bias + col + 1);
                *(float2*)(out + (size_t)m * Cdim + col) =
                    make_float2(acc[mt][nt][0] + b0, acc[mt][nt][1] + b1);
                *(float2*)(out + (size_t)(m + 8) * Cdim + col) =
                    make_float2(acc[mt][nt][2] + b0, acc[mt][nt][3] + b1);
            }
        }
    }
}

// ---------------------------------------------------------------------------
// Tensor-core partial kv with register-double-buffered global loads.
// ---------------------------------------------------------------------------
#define TROW 72

__global__ __launch_bounds__(128)
void kvp_tc()
{
    __shared__ __half skT[64][TROW];   // [e][seq]
    __shared__ __half svT[64][TROW];   // [d][seq]
    __shared__ float red[2][64];
    const int bh = blockIdx.x;
    const int prt = blockIdx.y;
    const int bb = bh >> 4, h = bh & 15;
    const int tid = threadIdx.x;
    const int lane = tid & 31;
    const int w = tid >> 5;
    const size_t base = (size_t)bb * Lseq * Cdim + h * En;
    const uint32_t skb = smem_u32(&skT[0][0]);
    const uint32_t svb = smem_u32(&svT[0][0]);

    const int a_row = (lane & 7) + ((lane >> 3) & 1) * 8;
    const int a_kq  = (lane >> 4) & 1;
    const int b_row = (lane & 7) + (lane >> 4) * 8;
    const int b_kq  = (lane >> 3) & 1;

    float acc[8][4] = {};
    float ks0 = 0.0f;
    const int e_id = tid & 63, zp = tid >> 6;

    int lseq[4], loct[4];
    #pragma unroll
    for (int p = 0; p < 4; p++) {
        int id = tid + p * 128;
        lseq[p] = id & 63;
        loct[p] = id >> 6;
    }

    uint4 pk[4], pv[4];
    {
        const int n0 = (prt * 7) * 64;
        #pragma unroll
        for (int p = 0; p < 4; p++) {
            size_t g = base + (size_t)(n0 + lseq[p]) * Cdim + loct[p] * 8;
            pk[p] = *(const uint4*)(g_kh + g);
            pv[p] = *(const uint4*)(g_vh + g);
        }
    }

    for (int t = 0; t < 7; t++) {
        __syncthreads();
        #pragma unroll
        for (int p = 0; p < 4; p++) {
            const __half* hk = (const __half*)&pk[p];
            const __half* hv = (const __half*)&pv[p];
            #pragma unroll
            for (int j = 0; j < 8; j++) {
                skT[loct[p] * 8 + j][lseq[p]] = hk[j];
                svT[loct[p] * 8 + j][lseq[p]] = hv[j];
            }
        }
        __syncthreads();

        if (t + 1 < 7) {
            const int n0 = (prt * 7 + t + 1) * 64;
            #pragma unroll
            for (int p = 0; p < 4; p++) {
                size_t g = base + (size_t)(n0 + lseq[p]) * Cdim + loct[p] * 8;
                pk[p] = *(const uint4*)(g_kh + g);
                pv[p] = *(const uint4*)(g_vh + g);
            }
        }

        #pragma unroll
        for (int ks = 0; ks < 4; ks++) {
            uint32_t ah[4];
            ldsm4(skb + (w * 16 + a_row) * (TROW * 2) + ks * 32 + a_kq * 16, ah);
            #pragma unroll
            for (int bt = 0; bt < 4; bt++) {
                uint32_t bh4[4];
                ldsm4(svb + (bt * 16 + b_row) * (TROW * 2) + ks * 32 + b_kq * 16, bh4);
                mma16816(acc[bt * 2],     ah, bh4[0], bh4[1]);
                mma16816(acc[bt * 2 + 1], ah, bh4[2], bh4[3]);
            }
        }
        #pragma unroll
        for (int s = 0; s < 32; s++)
            ks0 += __half2float(skT[e_id][zp * 32 + s]);
    }

    const int r4 = lane >> 2, c4 = lane & 3;
    float* dst = g_kvp[prt] + bh * (En * En);
    #pragma unroll
    for (int nt = 0; nt < 8; nt++) {
        int e = w * 16 + r4;
        int d = nt * 8 + c4 * 2;
        *(float2*)&dst[e * En + d]       = make_float2(acc[nt][0], acc[nt][1]);
        *(float2*)&dst[(e + 8) * En + d] = make_float2(acc[nt][2], acc[nt][3]);
    }

    __syncthreads();
    red[zp][e_id] = ks0;
    __syncthreads();
    if (tid < 64)
        g_ksp[prt][bh * En + tid] = red[0][tid] + red[1][tid];
}

// ---------------------------------------------------------------------------
// Wide reduce of partial kv/ksum
// ---------------------------------------------------------------------------
__global__ __launch_bounds__(256)
void kvred_kernel()
{
    const int gid = blockIdx.x * 256 + threadIdx.x;
    {
        int idx = gid * 4;
        float4 s = *(const float4*)&g_kvp[0][idx];
        #pragma unroll
        for (int p = 1; p < KVP; p++) {
            float4 t = *(const float4*)&g_kvp[p][idx];
            s.x += t.x; s.y += t.y; s.z += t.z; s.w += t.w;
        }
        *(float4*)&g_kv[idx] = s;
    }
    if (gid < 2048) {
        int idx = gid * 4;
        float4 s = *(const float4*)&g_ksp[0][idx];
        #pragma unroll
        for (int p = 1; p < KVP; p++) {
            float4 t = *(const float4*)&g_ksp[p][idx];
            s.x += t.x; s.y += t.y; s.z += t.z; s.w += t.w;
        }
        *(float4*)&g_ksum[idx] = s;
    }
}

// ---------------------------------------------------------------------------
// Tensor-core attn: out = (q_ @ kv) * z -> fp16. 4 token-tiles per block.
// ---------------------------------------------------------------------------
__global__ __launch_bounds__(128)
void attn_tc()
{
    __shared__ __half sq  [64][TROW];   // [token][e]
    __shared__ __half skvT[64][TROW];   // [d][e]
    __shared__ float sks[64];
    __shared__ float szp[2][64];
    __shared__ float sz[64];
    const int bh = blockIdx.y;
    const int bb = bh >> 4, h = bh & 15;
    const int tid = threadIdx.x;
    const int lane = tid & 31;
    const int w = tid >> 5;
    const uint32_t sqb = smem_u32(&sq[0][0]);
    const uint32_t skb = smem_u32(&skvT[0][0]);

    const int a_row = (lane & 7) + ((lane >> 3) & 1) * 8;
    const int a_kq  = (lane >> 4) & 1;
    const int b_row = (lane & 7) + (lane >> 4) * 8;
    const int b_kq  = (lane >> 3) & 1;

    #pragma unroll
    for (int p = 0; p < 8; p++) {
        int id = tid + p * 128;
        int e = id >> 4;
        int d0 = (id & 15) * 4;
        float4 v = *(const float4*)&g_kv[bh * (En * En) + e * En + d0];
        skvT[d0 + 0][e] = __float2half_rn(v.x);
        skvT[d0 + 1][e] = __float2half_rn(v.y);
        skvT[d0 + 2][e] = __float2half_rn(v.z);
        skvT[d0 + 3][e] = __float2half_rn(v.w);
    }
    if (tid < 16)
        *(float4*)&sks[tid * 4] = *(const float4*)&g_ksum[bh * En + tid * 4];

    const int tok_z = tid & 63, zp = tid >> 6;

    for (int t = 0; t < 4; t++) {
        const int tile = blockIdx.x * 4 + t;
        if (tile >= 49) break;
        const int n0 = tile * 64;

        __syncthreads();
        #pragma unroll
        for (int p = 0; p < 4; p++) {
            int id = tid + p * 128;
            int tok = id >> 3, oct = id & 7;
            size_t g = ((size_t)bb * Lseq + n0 + tok) * Cdim + h * En + oct * 8;
            *(uint4*)&sq[tok][oct * 8] = *(const uint4*)(g_qh + g);
        }
        __syncthreads();

        {
            float d = 0.0f;
            #pragma unroll
            for (int s = 0; s < 32; s++)
                d += __half2float(sq[tok_z][zp * 32 + s]) * sks[zp * 32 + s];
            szp[zp][tok_z] = d;
        }
        __syncthreads();
        if (tid < 64)
            sz[tid] = 1.0f / (szp[0][tid] + szp[1][tid] + EPS_V);
        __syncthreads();

        float acc[8][4] = {};
        #pragma unroll
        for (int ks = 0; ks < 4; ks++) {
            uint32_t ah[4];
            ldsm4(sqb + (w * 16 + a_row) * (TROW * 2) + ks * 32 + a_kq * 16, ah);
            #pragma unroll
            for (int bt = 0; bt < 4; bt++) {
                uint32_t bh4[4];
                ldsm4(skb + (bt * 16 + b_row) * (TROW * 2) + ks * 32 + b_kq * 16, bh4);
                mma16816(acc[bt * 2],     ah, bh4[0], bh4[1]);
                mma16816(acc[bt * 2 + 1], ah, bh4[2], bh4[3]);
            }
        }

        const int r4 = lane >> 2, c4 = lane & 3;
        #pragma unroll
        for (int nt = 0; nt < 8; nt++) {
            int trow = w * 16 + r4;
            int d = nt * 8 + c4 * 2;
            float z0 = sz[trow], z1 = sz[trow + 8];
            __half2 h01 = __floats2half2_rn(acc[nt][0] * z0, acc[nt][1] * z0);
            __half2 h23 = __floats2half2_rn(acc[nt][2] * z1, acc[nt][3] * z1);
            size_t g0 = ((size_t)bb * Lseq + n0 + trow) * Cdim + h * En + d;
            *(uint32_t*)(g_ah + g0)            = *(uint32_t*)&h01;
            *(uint32_t*)(g_ah + g0 + 8 * Cdim) = *(uint32_t*)&h23;
        }
    }
}

// ---------------------------------------------------------------------------
extern "C" void kernel_launch(void* const* d_in, const int* in_sizes, int n_in,
                              void* d_out, int out_size)
{
    const float* x      = (const float*)d_in[0];
    const float* w_qkv  = (const float*)d_in[1];
    const float* w_proj = (const float*)d_in[2];
    const float* b_proj = (const float*)d_in[3];
    float* out = (float*)d_out;

    cudaFuncSetAttribute(gemm_tc<0>, cudaFuncAttributeMaxDynamicSharedMemorySize, GEMM_SMEM);
    cudaFuncSetAttribute(gemm_tc<1>, cudaFuncAttributeMaxDynamicSharedMemorySize, GEMM_SMEM);

    __half *xh, *ah, *wqh, *wph;
    cudaGetSymbolAddress((void**)&xh,  g_xh);
    cudaGetSymbolAddress((void**)&ah,  g_ah);
    cudaGetSymbolAddress((void**)&wqh, g_wqh);
    cudaGetSymbolAddress((void**)&wph, g_wph);

    // 0) fused fp32 -> fp16 conversions (8 floats/thread)
    conv_all<<<(N4ALL + 511) / 512, 256>>>(
        (const float4*)x, (const float4*)w_qkv, (const float4*)w_proj);

    // 1) qkv = x @ w_qkv^T, fused q/k/v split + relu+scale
    gemm_tc<0><<<dim3(24, 196), 128, GEMM_SMEM>>>(xh, wqh, nullptr, nullptr);
    // 2) partial kv (+ k_sum) on tensor cores, then wide reduce
    kvp_tc<<<dim3(128, KVP), 128>>>();
    kvred_kernel<<<512, 256>>>();
    // 3) out = (q_ @ kv) * z on tensor cores -> fp16
    attn_tc<<<dim3(13, 128), 128>>>();
    // 4) final = attn @ w_proj^T + b_proj
    gemm_tc<1><<<dim3(8, 196), 128, GEMM_SMEM>>>(ah, wph, b_proj, out);
}

// round 17
// speedup vs baseline: 1.0216x; 1.0216x over previous
#include <cuda_runtime.h>
#include <cuda_fp16.h>
#include <cstdint>

// Problem constants
#define Cdim 1024
#define Hn   16
#define En   64
#define Mtok 25088          // B*N
#define Lseq 3136           // f*N
#define NBGRP 8
#define SCALE_Q 0.125f
#define EPS_V   1e-6f
#define KVP  7              // kv sequence partitions

#define N4X  (Mtok * (Cdim / 4))
#define N4WQ (3072 * Cdim / 4)
#define N4WP (Cdim * Cdim / 4)

// Scratch (static device memory)
__device__ float g_kv  [NBGRP * Hn * En * En];
__device__ float g_ksum[NBGRP * Hn * En];
__device__ float g_kvp [KVP][NBGRP * Hn * En * En];
__device__ float g_ksp [KVP][NBGRP * Hn * En];
// fp16 tensors
__device__ __half g_xh[(size_t)Mtok * Cdim];
__device__ __half g_qh[(size_t)Mtok * Cdim];
__device__ __half g_kh[(size_t)Mtok * Cdim];
__device__ __half g_vh[(size_t)Mtok * Cdim];
__device__ __half g_ah[(size_t)Mtok * Cdim];
__device__ __half g_wqh[3072 * Cdim];
__device__ __half g_wph[Cdim * Cdim];

// ---------------------------------------------------------------------------
// Helpers
// ---------------------------------------------------------------------------
__device__ __forceinline__ uint32_t smem_u32(const void* p) {
    uint32_t a;
    asm("{ .reg .u64 t; cvta.to.shared.u64 t, %1; cvt.u32.u64 %0, t; }" : "=r"(a) : "l"(p));
    return a;
}

__device__ __forceinline__ void mma16816(float* d, const uint32_t* a,
                                         uint32_t b0, uint32_t b1) {
    asm volatile(
        "mma.sync.aligned.m16n8k16.row.col.f32.f16.f16.f32 "
        "{%0,%1,%2,%3}, {%4,%5,%6,%7}, {%8,%9}, {%0,%1,%2,%3};"
        : "+f"(d[0]), "+f"(d[1]), "+f"(d[2]), "+f"(d[3])
        : "r"(a[0]), "r"(a[1]), "r"(a[2]), "r"(a[3]), "r"(b0), "r"(b1));
}

__device__ __forceinline__ void ldsm4(uint32_t addr, uint32_t* r) {
    asm volatile("ldmatrix.sync.aligned.m8n8.x4.shared.b16 {%0,%1,%2,%3}, [%4];"
                 : "=r"(r[0]), "=r"(r[1]), "=r"(r[2]), "=r"(r[3]) : "r"(addr));
}

#define CP16(dst, src) \
    asm volatile("cp.async.cg.shared.global [%0], [%1], 16;" :: "r"(dst), "l"(src))
#define CP_COMMIT() asm volatile("cp.async.commit_group;" ::: "memory")
#define CP_WAIT1()  asm volatile("cp.async.wait_group 1;" ::: "memory")

// Swizzled byte offset for 128-byte rows: quad (16B) XOR row&7
__device__ __forceinline__ uint32_t swz(uint32_t row, uint32_t quad) {
    return (row << 7) + ((quad ^ (row & 7)) << 4);
}

// ---------------------------------------------------------------------------
// Fused fp32 -> fp16 conversion (x, w_qkv, w_proj in one launch)
// ---------------------------------------------------------------------------
__global__ __launch_bounds__(256)
void conv_all(const float4* __restrict__ x, const float4* __restrict__ wq,
              const float4* __restrict__ wp)
{
    int i = blockIdx.x * 256 + threadIdx.x;
    const float4* src; __half* dst; int j;
    if (i < N4X)                { src = x;  dst = g_xh;  j = i; }
    else if (i < N4X + N4WQ)    { src = wq; dst = g_wqh; j = i - N4X; }
    else if (i < N4X + N4WQ + N4WP) { src = wp; dst = g_wph; j = i - N4X - N4WQ; }
    else return;
    float4 v = src[j];
    __half2 h01 = __floats2half2_rn(v.x, v.y);
    __half2 h23 = __floats2half2_rn(v.z, v.w);
    *(uint2*)&dst[(size_t)j * 4] = make_uint2(*(uint32_t*)&h01, *(uint32_t*)&h23);
}

// ---------------------------------------------------------------------------
// FP16 tensor-core NT GEMM. Block 128x128, K-chunk 64, 4 warps (2m x 2n),
// warp tile 64x64. cp.async for chunk c+2 spread one A/B PAIR per MMA
// iteration over the first 8 iterations (halved post-sync LSU burst, full
// lead time preserved); A frags double-buffered per k-step, B per iteration.
// NSTG=3, wait_group 1, 2 CTAs/SM.
// ---------------------------------------------------------------------------
#define ARR_SZ 16384
#define STG_B (2 * ARR_SZ)
#define NSTG 3
#define GEMM_SMEM (NSTG * STG_B)

template<int MODE>
__global__ __launch_bounds__(128, 2)
void gemm_tc(const __half* __restrict__ A_g,
             const __half* __restrict__ W_g,
             const float* __restrict__ bias, float* __restrict__ out)
{
    extern __shared__ __align__(128) char smem[];
    const uint32_t sbase = smem_u32(smem);
    const int tid  = threadIdx.x;
    const int lane = tid & 31;
    const int w    = tid >> 5;
    const int wm   = w & 1;
    const int wn   = w >> 1;
    const int m0 = blockIdx.y * 128;
    const int n0 = blockIdx.x * 128;

    const int a_row = (lane & 7) + ((lane >> 3) & 1) * 8;
    const int a_kq  = (lane >> 4) & 1;
    const int b_row = (lane & 7) + (lane >> 4) * 8;
    const int b_kq  = (lane >> 3) & 1;

    auto issue = [&](int c) {
        const uint32_t st = sbase + (c % NSTG) * STG_B;
        const int k0 = c * 64;
        #pragma unroll
        for (int p = 0; p < 8; p++) {
            int id = tid + p * 128;
            int row = id >> 3, quad = id & 7;
            uint32_t so = swz(row, quad);
            CP16(st + so, A_g + (size_t)(m0 + row) * Cdim + k0 + quad * 8);
            CP16(st + ARR_SZ + so, W_g + (size_t)(n0 + row) * Cdim + k0 + quad * 8);
        }
    };

    float acc[4][8][4];
    #pragma unroll
    for (int mt = 0; mt < 4; mt++)
        #pragma unroll
        for (int nt = 0; nt < 8; nt++)
            #pragma unroll
            for (int r = 0; r < 4; r++) acc[mt][nt][r] = 0.0f;

    issue(0); CP_COMMIT();
    issue(1); CP_COMMIT();

    for (int c = 0; c < 16; c++) {
        CP_WAIT1();
        __syncthreads();

        const bool pf = (c + 2 < 16);
        const uint32_t st2 = sbase + ((c + 2) % NSTG) * STG_B;
        const int k02 = (c + 2) * 64;

        const uint32_t st = sbase + (c % NSTG) * STG_B;
        const uint32_t sA = st, sB = st + ARR_SZ;

        // A double-buffer at ks granularity; B double-buffer per iteration
        uint32_t ah[2][4][4];
        #pragma unroll
        for (int mt = 0; mt < 4; mt++) {
            uint32_t row = wm * 64 + mt * 16 + a_row;
            ldsm4(sA + swz(row, 0 * 2 + a_kq), ah[0][mt]);
        }
        uint32_t bf[2][4];
        {
            uint32_t row = wn * 64 + 0 * 16 + b_row;
            ldsm4(sB + swz(row, 0 * 2 + b_kq), bf[0]);
        }
        #pragma unroll
        for (int it = 0; it < 16; it++) {
            const int ks = it >> 2, bt = it & 3;
            // spread next-chunk cp.async: one A/B pair per iteration (8 total)
            if (pf && it < 8) {
                int id = tid + it * 128;
                int row = id >> 3, quad = id & 7;
                uint32_t so = swz(row, quad);
                CP16(st2 + so, A_g + (size_t)(m0 + row) * Cdim + k02 + quad * 8);
                CP16(st2 + ARR_SZ + so, W_g + (size_t)(n0 + row) * Cdim + k02 + quad * 8);
            }
            // prefetch next B fragment
            if (it + 1 < 16) {
                const int ks2 = (it + 1) >> 2, bt2 = (it + 1) & 3;
                uint32_t row = wn * 64 + bt2 * 16 + b_row;
                ldsm4(sB + swz(row, ks2 * 2 + b_kq), bf[(it + 1) & 1]);
            }
            // prefetch one A fragment of ks+1 per iteration
            if (ks < 3) {
                const int mt = bt;
                uint32_t row = wm * 64 + mt * 16 + a_row;
                ldsm4(sA + swz(row, (ks + 1) * 2 + a_kq), ah[(ks + 1) & 1][mt]);
            }
            const uint32_t* bh = bf[it & 1];
            #pragma unroll
            for (int half = 0; half < 2; half++) {
                const int nt = bt * 2 + half;
                #pragma unroll
                for (int mt = 0; mt < 4; mt++)
                    mma16816(acc[mt][nt], ah[ks & 1][mt], bh[half * 2], bh[half * 2 + 1]);
            }
        }
        CP_COMMIT();
    }

    const int r4 = lane >> 2, c4 = lane & 3;
    if (MODE == 0) {
        const int sN = n0 >> 10;                 // 0:q 1:k 2:v
        __half* dst = (sN == 0) ? g_qh : (sN == 1) ? g_kh : g_vh;
        const int colb = (n0 & 1023) + wn * 64;
        #pragma unroll
        for (int mt = 0; mt < 4; mt++) {
            #pragma unroll
            for (int nt = 0; nt < 8; nt++) {
                float v0 = acc[mt][nt][0], v1 = acc[mt][nt][1];
                float v2 = acc[mt][nt][2], v3 = acc[mt][nt][3];
                if (sN < 2) {
                    v0 = fmaxf(v0, 0.0f) + SCALE_Q;
                    v1 = fmaxf(v1, 0.0f) + SCALE_Q;
                    v2 = fmaxf(v2, 0.0f) + SCALE_Q;
                    v3 = fmaxf(v3, 0.0f) + SCALE_Q;
                }
                int m = m0 + wm * 64 + mt * 16 + r4;
                int col = colb + nt * 8 + c4 * 2;
                __half2 h01 = __floats2half2_rn(v0, v1);
                __half2 h23 = __floats2half2_rn(v2, v3);
                *(uint32_t*)(dst + (size_t)m * Cdim + col)       = *(uint32_t*)&h01;
                *(uint32_t*)(dst + (size_t)(m + 8) * Cdim + col) = *(uint32_t*)&h23;
            }
        }
    } else {
        #pragma unroll
        for (int mt = 0; mt < 4; mt++) {
            #pragma unroll
            for (int nt = 0; nt < 8; nt++) {
                int m = m0 + wm * 64 + mt * 16 + r4;
                int col = n0 + wn * 64 + nt * 8 + c4 * 2;
                float b0 = __ldg(bias + col), b1 = __ldg(bias + col + 1);
                *(float2*)(out + (size_t)m * Cdim + col) =
                    make_float2(acc[mt][nt][0] + b0, acc[mt][nt][1] + b1);
                *(float2*)(out + (size_t)(m + 8) * Cdim + col) =
                    make_float2(acc[mt][nt][2] + b0, acc[mt][nt][3] + b1);
            }
        }
    }
}

// ---------------------------------------------------------------------------
// Tensor-core partial kv with register-double-buffered global loads.
// ---------------------------------------------------------------------------
#define TROW 72

__global__ __launch_bounds__(128)
void kvp_tc()
{
    __shared__ __half skT[64][TROW];   // [e][seq]
    __shared__ __half svT[64][TROW];   // [d][seq]
    __shared__ float red[2][64];
    const int bh = blockIdx.x;
    const int prt = blockIdx.y;
    const int bb = bh >> 4, h = bh & 15;
    const int tid = threadIdx.x;
    const int lane = tid & 31;
    const int w = tid >> 5;
    const size_t base = (size_t)bb * Lseq * Cdim + h * En;
    const uint32_t skb = smem_u32(&skT[0][0]);
    const uint32_t svb = smem_u32(&svT[0][0]);

    const int a_row = (lane & 7) + ((lane >> 3) & 1) * 8;
    const int a_kq  = (lane >> 4) & 1;
    const int b_row = (lane & 7) + (lane >> 4) * 8;
    const int b_kq  = (lane >> 3) & 1;

    float acc[8][4] = {};
    float ks0 = 0.0f;
    const int e_id = tid & 63, zp = tid >> 6;

    int lseq[4], loct[4];
    #pragma unroll
    for (int p = 0; p < 4; p++) {
        int id = tid + p * 128;
        lseq[p] = id & 63;
        loct[p] = id >> 6;
    }

    uint4 pk[4], pv[4];
    {
        const int n0 = (prt * 7) * 64;
        #pragma unroll
        for (int p = 0; p < 4; p++) {
            size_t g = base + (size_t)(n0 + lseq[p]) * Cdim + loct[p] * 8;
            pk[p] = *(const uint4*)(g_kh + g);
            pv[p] = *(const uint4*)(g_vh + g);
        }
    }

    for (int t = 0; t < 7; t++) {
        __syncthreads();
        #pragma unroll
        for (int p = 0; p < 4; p++) {
            const __half* hk = (const __half*)&pk[p];
            const __half* hv = (const __half*)&pv[p];
            #pragma unroll
            for (int j = 0; j < 8; j++) {
                skT[loct[p] * 8 + j][lseq[p]] = hk[j];
                svT[loct[p] * 8 + j][lseq[p]] = hv[j];
            }
        }
        __syncthreads();

        if (t + 1 < 7) {
            const int n0 = (prt * 7 + t + 1) * 64;
            #pragma unroll
            for (int p = 0; p < 4; p++) {
                size_t g = base + (size_t)(n0 + lseq[p]) * Cdim + loct[p] * 8;
                pk[p] = *(const uint4*)(g_kh + g);
                pv[p] = *(const uint4*)(g_vh + g);
            }
        }

        #pragma unroll
        for (int ks = 0; ks < 4; ks++) {
            uint32_t ah[4];
            ldsm4(skb + (w * 16 + a_row) * (TROW * 2) + ks * 32 + a_kq * 16, ah);
            #pragma unroll
            for (int bt = 0; bt < 4; bt++) {
                uint32_t bh4[4];
                ldsm4(svb + (bt * 16 + b_row) * (TROW * 2) + ks * 32 + b_kq * 16, bh4);
                mma16816(acc[bt * 2],     ah, bh4[0], bh4[1]);
                mma16816(acc[bt * 2 + 1], ah, bh4[2], bh4[3]);
            }
        }
        #pragma unroll
        for (int s = 0; s < 32; s++)
            ks0 += __half2float(skT[e_id][zp * 32 + s]);
    }

    const int r4 = lane >> 2, c4 = lane & 3;
    float* dst = g_kvp[prt] + bh * (En * En);
    #pragma unroll
    for (int nt = 0; nt < 8; nt++) {
        int e = w * 16 + r4;
        int d = nt * 8 + c4 * 2;
        *(float2*)&dst[e * En + d]       = make_float2(acc[nt][0], acc[nt][1]);
        *(float2*)&dst[(e + 8) * En + d] = make_float2(acc[nt][2], acc[nt][3]);
    }

    __syncthreads();
    red[zp][e_id] = ks0;
    __syncthreads();
    if (tid < 64)
        g_ksp[prt][bh * En + tid] = red[0][tid] + red[1][tid];
}

// ---------------------------------------------------------------------------
// Wide reduce of partial kv/ksum
// ---------------------------------------------------------------------------
__global__ __launch_bounds__(256)
void kvred_kernel()
{
    const int gid = blockIdx.x * 256 + threadIdx.x;
    {
        int idx = gid * 4;
        float4 s = *(const float4*)&g_kvp[0][idx];
        #pragma unroll
        for (int p = 1; p < KVP; p++) {
            float4 t = *(const float4*)&g_kvp[p][idx];
            s.x += t.x; s.y += t.y; s.z += t.z; s.w += t.w;
        }
        *(float4*)&g_kv[idx] = s;
    }
    if (gid < 2048) {
        int idx = gid * 4;
        float4 s = *(const float4*)&g_ksp[0][idx];
        #pragma unroll
        for (int p = 1; p < KVP; p++) {
            float4 t = *(const float4*)&g_ksp[p][idx];
            s.x += t.x; s.y += t.y; s.z += t.z; s.w += t.w;
        }
        *(float4*)&g_ksum[idx] = s;
    }
}

// ---------------------------------------------------------------------------
// Tensor-core attn: out = (q_ @ kv) * z -> fp16. 4 token-tiles per block.
// ---------------------------------------------------------------------------
__global__ __launch_bounds__(128)
void attn_tc()
{
    __shared__ __half sq  [64][TROW];   // [token][e]
    __shared__ __half skvT[64][TROW];   // [d][e]
    __shared__ float sks[64];
    __shared__ float szp[2][64];
    __shared__ float sz[64];
    const int bh = blockIdx.y;
    const int bb = bh >> 4, h = bh & 15;
    const int tid = threadIdx.x;
    const int lane = tid & 31;
    const int w = tid >> 5;
    const uint32_t sqb = smem_u32(&sq[0][0]);
    const uint32_t skb = smem_u32(&skvT[0][0]);

    const int a_row = (lane & 7) + ((lane >> 3) & 1) * 8;
    const int a_kq  = (lane >> 4) & 1;
    const int b_row = (lane & 7) + (lane >> 4) * 8;
    const int b_kq  = (lane >> 3) & 1;

    #pragma unroll
    for (int p = 0; p < 8; p++) {
        int id = tid + p * 128;
        int e = id >> 4;
        int d0 = (id & 15) * 4;
        float4 v = *(const float4*)&g_kv[bh * (En * En) + e * En + d0];
        skvT[d0 + 0][e] = __float2half_rn(v.x);
        skvT[d0 + 1][e] = __float2half_rn(v.y);
        skvT[d0 + 2][e] = __float2half_rn(v.z);
        skvT[d0 + 3][e] = __float2half_rn(v.w);
    }
    if (tid < 16)
        *(float4*)&sks[tid * 4] = *(const float4*)&g_ksum[bh * En + tid * 4];

    const int tok_z = tid & 63, zp = tid >> 6;

    for (int t = 0; t < 4; t++) {
        const int tile = blockIdx.x * 4 + t;
        if (tile >= 49) break;
        const int n0 = tile * 64;

        __syncthreads();
        #pragma unroll
        for (int p = 0; p < 4; p++) {
            int id = tid + p * 128;
            int tok = id >> 3, oct = id & 7;
            size_t g = ((size_t)bb * Lseq + n0 + tok) * Cdim + h * En + oct * 8;
            *(uint4*)&sq[tok][oct * 8] = *(const uint4*)(g_qh + g);
        }
        __syncthreads();

        {
            float d = 0.0f;
            #pragma unroll
            for (int s = 0; s < 32; s++)
                d += __half2float(sq[tok_z][zp * 32 + s]) * sks[zp * 32 + s];
            szp[zp][tok_z] = d;
        }
        __syncthreads();
        if (tid < 64)
            sz[tid] = 1.0f / (szp[0][tid] + szp[1][tid] + EPS_V);
        __syncthreads();

        float acc[8][4] = {};
        #pragma unroll
        for (int ks = 0; ks < 4; ks++) {
            uint32_t ah[4];
            ldsm4(sqb + (w * 16 + a_row) * (TROW * 2) + ks * 32 + a_kq * 16, ah);
            #pragma unroll
            for (int bt = 0; bt < 4; bt++) {
                uint32_t bh4[4];
                ldsm4(skb + (bt * 16 + b_row) * (TROW * 2) + ks * 32 + b_kq * 16, bh4);
                mma16816(acc[bt * 2],     ah, bh4[0], bh4[1]);
                mma16816(acc[bt * 2 + 1], ah, bh4[2], bh4[3]);
            }
        }

        const int r4 = lane >> 2, c4 = lane & 3;
        #pragma unroll
        for (int nt = 0; nt < 8; nt++) {
            int trow = w * 16 + r4;
            int d = nt * 8 + c4 * 2;
            float z0 = sz[trow], z1 = sz[trow + 8];
            __half2 h01 = __floats2half2_rn(acc[nt][0] * z0, acc[nt][1] * z0);
            __half2 h23 = __floats2half2_rn(acc[nt][2] * z1, acc[nt][3] * z1);
            size_t g0 = ((size_t)bb * Lseq + n0 + trow) * Cdim + h * En + d;
            *(uint32_t*)(g_ah + g0)            = *(uint32_t*)&h01;
            *(uint32_t*)(g_ah + g0 + 8 * Cdim) = *(uint32_t*)&h23;
        }
    }
}

// ---------------------------------------------------------------------------
extern "C" void kernel_launch(void* const* d_in, const int* in_sizes, int n_in,
                              void* d_out, int out_size)
{
    const float* x      = (const float*)d_in[0];
    const float* w_qkv  = (const float*)d_in[1];
    const float* w_proj = (const float*)d_in[2];
    const float* b_proj = (const float*)d_in[3];
    float* out = (float*)d_out;

    cudaFuncSetAttribute(gemm_tc<0>, cudaFuncAttributeMaxDynamicSharedMemorySize, GEMM_SMEM);
    cudaFuncSetAttribute(gemm_tc<1>, cudaFuncAttributeMaxDynamicSharedMemorySize, GEMM_SMEM);

    __half *xh, *ah, *wqh, *wph;
    cudaGetSymbolAddress((void**)&xh,  g_xh);
    cudaGetSymbolAddress((void**)&ah,  g_ah);
    cudaGetSymbolAddress((void**)&wqh, g_wqh);
    cudaGetSymbolAddress((void**)&wph, g_wph);

    // 0) fused fp32 -> fp16 conversions
    {
        int total = N4X + N4WQ + N4WP;
        conv_all<<<(total + 255) / 256, 256>>>(
            (const float4*)x, (const float4*)w_qkv, (const float4*)w_proj);
    }

    // 1) qkv = x @ w_qkv^T, fused q/k/v split + relu+scale
    gemm_tc<0><<<dim3(24, 196), 128, GEMM_SMEM>>>(xh, wqh, nullptr, nullptr);
    // 2) partial kv (+ k_sum) on tensor cores, then wide reduce
    kvp_tc<<<dim3(128, KVP), 128>>>();
    kvred_kernel<<<512, 256>>>();
    // 3) out = (q_ @ kv) * z on tensor cores -> fp16
    attn_tc<<<dim3(13, 128), 128>>>();
    // 4) final = attn @ w_proj^T + b_proj
    gemm_tc<1><<<dim3(8, 196), 128, GEMM_SMEM>>>(ah, wph, b_proj, out);
}